// round 2
// baseline (speedup 1.0000x reference)
#include <cuda_runtime.h>
#include <cstdint>

// AttentionDownsampler v2: fused single-read, fused logits.
//   hr_feats (8,384,112,112) fp32 -> out (8,384,16,16) fp32
// Patches are non-overlapping 7x7 tiles (stride == K == 7).
// One CTA per (b, ph, pw) patch. Thread (p, j): p = tid>>3 owns one of the
// 49 patch positions, j = tid&7 its channel phase. The dot product with aw
// is accumulated DURING the load, then reduced across the 8-lane j-group,
// eliminating the separate logits smem pass and all per-element index math.

#define DIM     384
#define KS      7
#define NP      49
#define HW      112
#define PLANE   (HW * HW)      // 12544
#define FINALN  16
#define THREADS 392            // 49 * 8
#define CPT     48             // channels per thread: DIM/8
#define STRIDE  392            // smem row stride (mod 32 == 8): conflict-free
#define DROP_P  0.2f

#define SMEM_FLOATS (NP * STRIDE + NP + NP)
#define SMEM_BYTES  (SMEM_FLOATS * 4)

__global__ void __launch_bounds__(THREADS, 2)
attn_downsampler_kernel(const float* __restrict__ hr,
                        const float* __restrict__ du,
                        const float* __restrict__ aw,
                        const float* __restrict__ ab,
                        const float* __restrict__ wmat,
                        const float* __restrict__ bmat,
                        float* __restrict__ out)
{
    extern __shared__ float smem[];
    float* tile = smem;                  // [NP][STRIDE]  tile[p*STRIDE + c]
    float* lsh  = tile + NP * STRIDE;    // [NP] raw dot products
    float* attn = lsh + NP;              // [NP] softmax weights

    const int bid = blockIdx.x;
    const int pw  = bid & 15;
    const int ph  = (bid >> 4) & 15;
    const int pb  = bid >> 8;

    const int tid = threadIdx.x;
    const int j   = tid & 7;             // channel phase 0..7
    const int p   = tid >> 3;            // patch position 0..48
    const int dy  = p / KS;              // once per thread
    const int dx  = p - dy * KS;

    // global pointer for (c = j, this p)
    const float* gp = hr + (size_t)pb * DIM * PLANE
                         + (size_t)j * PLANE
                         + (size_t)(ph * KS + dy) * HW + (pw * KS + dx);
    float* trow = tile + p * STRIDE + j;

    // ---- fused load + dot-product: 48 channels per thread ----
    float s = 0.f;
    #pragma unroll
    for (int t = 0; t < CPT; t++) {
        float v = __ldg(gp + (size_t)t * 8 * PLANE);
        s = fmaf(v, __ldg(aw + j + 8 * t), s);
        trow[8 * t] = v;
    }

    // reduce over the 8-lane j-group (lanes g*8 .. g*8+7 of this warp)
    const unsigned gmask = 0xFFu << (tid & 24);
    s += __shfl_xor_sync(gmask, s, 1);
    s += __shfl_xor_sync(gmask, s, 2);
    s += __shfl_xor_sync(gmask, s, 4);
    if (j == 0) lsh[p] = s;
    __syncthreads();

    // ---- masked affine + softmax over 49 (warp 0) ----
    if (tid < 32) {
        const int   lane = tid;
        const float m    = (du[(pb * FINALN + ph) * FINALN + pw] > DROP_P) ? 1.f : 0.f;
        const float abv  = ab[0];
        const int p1 = lane + 32;
        float v0 = -1e30f, v1 = -1e30f;
        if (lane < NP) v0 = (lsh[lane] + abv) * m * wmat[lane] + bmat[lane];
        if (p1   < NP) v1 = (lsh[p1]   + abv) * m * wmat[p1]   + bmat[p1];
        float mx = fmaxf(v0, v1);
        #pragma unroll
        for (int o = 16; o; o >>= 1)
            mx = fmaxf(mx, __shfl_xor_sync(0xffffffffu, mx, o));
        float e0 = (lane < NP) ? __expf(v0 - mx) : 0.f;
        float e1 = (p1   < NP) ? __expf(v1 - mx) : 0.f;
        float ss = e0 + e1;
        #pragma unroll
        for (int o = 16; o; o >>= 1)
            ss += __shfl_xor_sync(0xffffffffu, ss, o);
        const float inv = 1.f / ss;
        if (lane < NP) attn[lane] = e0 * inv;
        if (p1   < NP) attn[p1]   = e1 * inv;
    }
    __syncthreads();

    // ---- output: one channel per thread (tid < 384) ----
    if (tid < DIM) {
        float acc = 0.f;
        #pragma unroll
        for (int q = 0; q < NP; q++)
            acc = fmaf(tile[q * STRIDE + tid], attn[q], acc);
        out[((size_t)(pb * DIM + tid) * FINALN + ph) * FINALN + pw] = acc;
    }
}

extern "C" void kernel_launch(void* const* d_in, const int* in_sizes, int n_in,
                              void* d_out, int out_size)
{
    const float* hr   = (const float*)d_in[0];   // (8,384,112,112)
    // d_in[1] = guidance (unused)
    const float* du   = (const float*)d_in[2];   // (8,16,16,1)
    const float* aw   = (const float*)d_in[3];   // (384,)
    const float* ab   = (const float*)d_in[4];   // (1,)
    const float* wmat = (const float*)d_in[5];   // (7,7)
    const float* bmat = (const float*)d_in[6];   // (7,7)
    float* out = (float*)d_out;                  // (8,384,16,16)

    cudaFuncSetAttribute(attn_downsampler_kernel,
                         cudaFuncAttributeMaxDynamicSharedMemorySize, SMEM_BYTES);

    dim3 grid(8 * FINALN * FINALN);              // 2048 patches
    attn_downsampler_kernel<<<grid, THREADS, SMEM_BYTES>>>(
        hr, du, aw, ab, wmat, bmat, out);
}

// round 3
// speedup vs baseline: 1.1802x; 1.1802x over previous
#include <cuda_runtime.h>
#include <cstdint>

// AttentionDownsampler v3: single coalesced read.
// Insight: logits[b,ph,pw,p] = pixel_dot[b, ph*7+dy, pw*7+dx] + ab, where
// pixel_dot = sum_c hr[b,c,y,x]*aw[c] is separable per channel. So CTAs can
// split channels, stream rows with perfect coalescing, exchange tiny per-pixel
// dot partials through global memory, and finish from their smem tiles.
//
// CTA = (b, ph, cg):  cg = 16 channel-groups x 24 channels.
//   Phase 1: load 24 ch x 7 rows x 112 floats (448B contiguous rows) -> smem,
//            accumulate pixel_dot partial, publish to g_part, bump counter.
//   Spin:    wait until all 16 groups of this (b,ph) slab published.
//   Phase 2: sum partials -> pixel_dot, softmax per patch, epilogue from smem.

#define DIM     384
#define KS      7
#define NP      49
#define HW      112
#define PLANE   (HW * HW)
#define FN      16
#define NSLAB   (8 * FN)          // 128 (b, ph) slabs
#define NCG     16                // channel groups per slab
#define CPG     24                // channels per group
#define SLABPIX (KS * HW)         // 784 pixels per slab row-band
#define THREADS 448               // (x:112, cc:4)
#define DROP_P  0.2f

// dynamic smem carve: tile[CPG*KS*HW] + pd_s[784] + attn_s[784] + red_s[448]
#define TILE_F   (CPG * KS * HW)  // 18816
#define SMEM_F   (TILE_F + SLABPIX + FN * NP + 4 * HW)
#define SMEM_B   (SMEM_F * 4)     // 83328 bytes

__device__ float g_part[(size_t)NSLAB * NCG * SLABPIX];
__device__ int   g_cnt[NSLAB];

__global__ void zero_cnt_kernel()
{
    if (threadIdx.x < NSLAB) g_cnt[threadIdx.x] = 0;
}

__global__ void __launch_bounds__(THREADS, 2)
attn_downsampler_kernel(const float* __restrict__ hr,
                        const float* __restrict__ du,
                        const float* __restrict__ aw,
                        const float* __restrict__ ab,
                        const float* __restrict__ wmat,
                        const float* __restrict__ bmat,
                        float* __restrict__ out)
{
    extern __shared__ float smem[];
    float* tile   = smem;                    // [CPG][KS][HW]
    float* pd_s   = tile + TILE_F;           // [784]
    float* attn_s = pd_s + SLABPIX;          // [16][49]
    float* red_s  = attn_s + FN * NP;        // [4][112]

    const int bid   = blockIdx.x;
    const int cg    = bid & (NCG - 1);
    const int slab  = bid >> 4;              // b*16 + ph
    const int ph    = slab & (FN - 1);
    const int b     = slab >> 4;
    const int cbase = cg * CPG;

    const int tid = threadIdx.x;
    const int x   = tid % HW;                // column 0..111
    const int cc  = tid / HW;                // channel phase 0..3

    // zero the per-CTA pixel-dot accumulator
    for (int i = tid; i < SLABPIX; i += THREADS) pd_s[i] = 0.f;
    __syncthreads();

    // ---- phase 1: coalesced load + pixel-dot partial ----
    float pdacc[KS];
    #pragma unroll
    for (int dy = 0; dy < KS; dy++) pdacc[dy] = 0.f;

    const float* hrb = hr + (size_t)b * DIM * PLANE + (size_t)(ph * KS) * HW + x;
    #pragma unroll
    for (int g = 0; g < 6; g++) {
        const int lc = cc * 6 + g;           // local channel 0..23
        const int c  = cbase + lc;
        const float* rp = hrb + (size_t)c * PLANE;
        const float  a  = __ldg(aw + c);
        float* ts = tile + lc * KS * HW + x;
        #pragma unroll
        for (int dy = 0; dy < KS; dy++) {
            float v = __ldg(rp + dy * HW);   // 448B contiguous per (c,dy) row
            ts[dy * HW] = v;
            pdacc[dy] = fmaf(v, a, pdacc[dy]);
        }
    }
    #pragma unroll
    for (int dy = 0; dy < KS; dy++)
        atomicAdd(&pd_s[dy * HW + x], pdacc[dy]);   // 4-way same-addr, cheap
    __syncthreads();

    // publish this group's partial, then arrive
    float* slot = g_part + ((size_t)slab * NCG + cg) * SLABPIX;
    for (int i = tid; i < SLABPIX; i += THREADS) slot[i] = pd_s[i];
    __threadfence();
    __syncthreads();
    if (tid == 0) {
        atomicAdd(&g_cnt[slab], 1);          // arrive BEFORE spinning
        while (atomicAdd(&g_cnt[slab], 0) < NCG) __nanosleep(128);
        __threadfence();
    }
    __syncthreads();

    // ---- sum the 16 partials -> full pixel_dot for this slab ----
    for (int i = tid; i < SLABPIX; i += THREADS) {
        const float* pp = g_part + (size_t)slab * NCG * SLABPIX + i;
        float s = 0.f;
        #pragma unroll
        for (int k = 0; k < NCG; k++) s += pp[k * SLABPIX];
        pd_s[i] = s;
    }
    __syncthreads();

    // ---- softmax per patch (warp w handles pw = w, w+14) ----
    {
        const int wid = tid >> 5, lane = tid & 31;
        const float abv = __ldg(ab);
        for (int pw = wid; pw < FN; pw += 14) {
            const float m = (__ldg(du + (b * FN + ph) * FN + pw) > DROP_P) ? 1.f : 0.f;
            const int p0 = lane, p1 = lane + 32;
            float v0 = -1e30f, v1 = -1e30f;
            if (p0 < NP) {
                int dy = p0 / KS, dx = p0 - dy * KS;
                v0 = (pd_s[dy * HW + pw * KS + dx] + abv) * m * __ldg(wmat + p0) + __ldg(bmat + p0);
            }
            if (p1 < NP) {
                int dy = p1 / KS, dx = p1 - dy * KS;
                v1 = (pd_s[dy * HW + pw * KS + dx] + abv) * m * __ldg(wmat + p1) + __ldg(bmat + p1);
            }
            float mx = fmaxf(v0, v1);
            #pragma unroll
            for (int o = 16; o; o >>= 1)
                mx = fmaxf(mx, __shfl_xor_sync(0xffffffffu, mx, o));
            float e0 = (p0 < NP) ? __expf(v0 - mx) : 0.f;
            float e1 = (p1 < NP) ? __expf(v1 - mx) : 0.f;
            float ss = e0 + e1;
            #pragma unroll
            for (int o = 16; o; o >>= 1)
                ss += __shfl_xor_sync(0xffffffffu, ss, o);
            const float inv = 1.f / ss;
            if (p0 < NP) attn_s[pw * NP + p0] = e0 * inv;
            if (p1 < NP) attn_s[pw * NP + p1] = e1 * inv;
        }
    }
    __syncthreads();

    // ---- phase 2: epilogue from smem tile ----
    const int pw = x / KS;
    const int dx = x - pw * KS;
    float a7[KS];                             // this column's 7 attn weights
    #pragma unroll
    for (int dy = 0; dy < KS; dy++)
        a7[dy] = attn_s[pw * NP + dy * KS + dx];

    #pragma unroll
    for (int g = 0; g < 6; g++) {
        const int lc = cc * 6 + g;
        const float* ts = tile + lc * KS * HW + x;
        float acc = 0.f;
        #pragma unroll
        for (int dy = 0; dy < KS; dy++)
            acc = fmaf(ts[dy * HW], a7[dy], acc);
        red_s[cc * HW + x] = acc;
        __syncthreads();
        if (tid < 64) {                       // (cc2, pw2): sum 7 columns
            const int cc2 = tid >> 4, pw2 = tid & 15;
            const float* r = red_s + cc2 * HW + pw2 * KS;
            float s = r[0] + r[1] + r[2] + r[3] + r[4] + r[5] + r[6];
            const int c2 = cbase + cc2 * 6 + g;
            out[((size_t)(b * DIM + c2) * FN + ph) * FN + pw2] = s;
        }
        __syncthreads();
    }
}

extern "C" void kernel_launch(void* const* d_in, const int* in_sizes, int n_in,
                              void* d_out, int out_size)
{
    const float* hr   = (const float*)d_in[0];   // (8,384,112,112)
    // d_in[1] = guidance (unused)
    const float* du   = (const float*)d_in[2];   // (8,16,16,1)
    const float* aw   = (const float*)d_in[3];   // (384,)
    const float* ab   = (const float*)d_in[4];   // (1,)
    const float* wmat = (const float*)d_in[5];   // (7,7)
    const float* bmat = (const float*)d_in[6];   // (7,7)
    float* out = (float*)d_out;                  // (8,384,16,16)

    cudaFuncSetAttribute(attn_downsampler_kernel,
                         cudaFuncAttributeMaxDynamicSharedMemorySize, SMEM_B);

    zero_cnt_kernel<<<1, 128>>>();
    attn_downsampler_kernel<<<NSLAB * NCG, THREADS, SMEM_B>>>(
        hr, du, aw, ab, wmat, bmat, out);
}